// round 16
// baseline (speedup 1.0000x reference)
#include <cuda_runtime.h>
#include <cstdint>

typedef unsigned long long ull;

#define IMG_W 512
#define OUT_W 507
#define NSTR  3       // strips per image
#define STRIP 169     // output rows per strip (3*169 = 507 exact)
#define NROWS 174     // input rows per strip (STRIP + 5), divisible by 6
#define SEGF  72      // floats per warp row segment (64 + 6 halo + 2 pad)
#define NSLOT 6       // smem ring slots per warp

// ---------------- device-global scratch (no allocs) --------------------------
__device__ float    g_mnp[512], g_mxp[512];   // per-block minmax partials
__device__ float    g_part[512];              // per-block ssim partials
__device__ unsigned g_bar;                    // phase-1 barrier; reset by last block
__device__ unsigned g_done;                   // final counter;  reset by last block

// ---------------- packed f32x2 helpers (sm_103a) ------------------------------
static __device__ __forceinline__ ull pk2(float a, float b){
    ull r; asm("mov.b64 %0, {%1, %2};" : "=l"(r) : "f"(a), "f"(b)); return r;
}
static __device__ __forceinline__ ull mul2(ull a, ull b){
    ull r; asm("mul.rn.f32x2 %0, %1, %2;" : "=l"(r) : "l"(a), "l"(b)); return r;
}
static __device__ __forceinline__ ull add2(ull a, ull b){
    ull r; asm("add.rn.f32x2 %0, %1, %2;" : "=l"(r) : "l"(a), "l"(b)); return r;
}
static __device__ __forceinline__ ull fma2(ull a, ull b, ull c){
    ull r; asm("fma.rn.f32x2 %0, %1, %2, %3;" : "=l"(r) : "l"(a), "l"(b), "l"(c)); return r;
}
static __device__ __forceinline__ float lo2(ull a){ return __uint_as_float((unsigned)a); }
static __device__ __forceinline__ float hi2(ull a){ return __uint_as_float((unsigned)(a >> 32)); }

static __device__ __forceinline__ void cpa16(unsigned dst, const void* src){
    asm volatile("cp.async.ca.shared.global [%0], [%1], 16;" :: "r"(dst), "l"(src) : "memory");
}
static __device__ __forceinline__ void cpa_commit(){
    asm volatile("cp.async.commit_group;" ::: "memory");
}
static __device__ __forceinline__ void cpa_wait2(){
    asm volatile("cp.async.wait_group 2;" ::: "memory");
}

// ---------------- gaussian weights (w_size=6, sigma=1.5, normalized) ---------
#define GW0 0.03802585f
#define GW1 0.11551231f
#define GW2 0.22498725f
#define GW3 0.28097506f

// 6-tap packed MAC: taps [GW0,GW1,GW2,GW3,GW2,GW1]
#define HMAC(d, v0, v1, v2, v3, v4, v5) \
    d = mul2((v0), W0); d = fma2((v1), W1, d); d = fma2((v2), W2, d); \
    d = fma2((v3), W3, d); d = fma2((v4), W2, d); d = fma2((v5), W1, d)

// Compute one row from smem slot P%6; horizontal conv into ring[P]; optional output.
#define ROW_COMPUTE(P, DOOUT) do { \
    { \
        const float* bx_ = &swx[(P)%NSLOT][lane2]; \
        const float* by_ = &swy[(P)%NSLOT][lane2]; \
        float2 X0_ = *(const float2*)(bx_    ); \
        float2 X1_ = *(const float2*)(bx_ + 2); \
        float2 X2_ = *(const float2*)(bx_ + 4); \
        float2 X3_ = *(const float2*)(bx_ + 6); \
        float2 Y0_ = *(const float2*)(by_    ); \
        float2 Y1_ = *(const float2*)(by_ + 2); \
        float2 Y2_ = *(const float2*)(by_ + 4); \
        float2 Y3_ = *(const float2*)(by_ + 6); \
        ull xp0_ = pk2(X0_.x, X0_.y), xp1_ = pk2(X1_.x, X1_.y); \
        ull xp2_ = pk2(X2_.x, X2_.y), xp3_ = pk2(X3_.x, X3_.y); \
        ull yp0_ = pk2(Y0_.x, Y0_.y), yp1_ = pk2(Y1_.x, Y1_.y); \
        ull yp2_ = pk2(Y2_.x, Y2_.y), yp3_ = pk2(Y3_.x, Y3_.y); \
        ull pp0_ = fma2(yp0_, yp0_, mul2(xp0_, xp0_)); \
        ull pp1_ = fma2(yp1_, yp1_, mul2(xp1_, xp1_)); \
        ull pp2_ = fma2(yp2_, yp2_, mul2(xp2_, xp2_)); \
        ull pp3_ = fma2(yp3_, yp3_, mul2(xp3_, xp3_)); \
        ull qq0_ = mul2(xp0_, yp0_), qq1_ = mul2(xp1_, yp1_); \
        ull qq2_ = mul2(xp2_, yp2_), qq3_ = mul2(xp3_, yp3_); \
        { ull d_; HMAC(d_, xp0_, pk2(X0_.y, X1_.x), xp1_, pk2(X1_.y, X2_.x), xp2_, pk2(X2_.y, X3_.x)); ring[(P)][0] = d_; } \
        { ull d_; HMAC(d_, yp0_, pk2(Y0_.y, Y1_.x), yp1_, pk2(Y1_.y, Y2_.x), yp2_, pk2(Y2_.y, Y3_.x)); ring[(P)][1] = d_; } \
        { ull d_; HMAC(d_, pp0_, pk2(hi2(pp0_), lo2(pp1_)), pp1_, pk2(hi2(pp1_), lo2(pp2_)), pp2_, pk2(hi2(pp2_), lo2(pp3_))); ring[(P)][2] = d_; } \
        { ull d_; HMAC(d_, qq0_, pk2(hi2(qq0_), lo2(qq1_)), qq1_, pk2(hi2(qq1_), lo2(qq2_)), qq2_, pk2(hi2(qq2_), lo2(qq3_))); ring[(P)][3] = d_; } \
    } \
    if (DOOUT){ \
        ull v0_, v1_, v2_, v3_; \
        HMAC(v0_, ring[((P)+1)%6][0], ring[((P)+2)%6][0], ring[((P)+3)%6][0], ring[((P)+4)%6][0], ring[((P)+5)%6][0], ring[(P)][0]); \
        HMAC(v1_, ring[((P)+1)%6][1], ring[((P)+2)%6][1], ring[((P)+3)%6][1], ring[((P)+4)%6][1], ring[((P)+5)%6][1], ring[(P)][1]); \
        HMAC(v2_, ring[((P)+1)%6][2], ring[((P)+2)%6][2], ring[((P)+3)%6][2], ring[((P)+4)%6][2], ring[((P)+5)%6][2], ring[(P)][2]); \
        HMAC(v3_, ring[((P)+1)%6][3], ring[((P)+2)%6][3], ring[((P)+3)%6][3], ring[((P)+4)%6][3], ring[((P)+5)%6][3], ring[(P)][3]); \
        ull mu12_ = mul2(v0_, v1_); \
        ull msum_ = fma2(v1_, v1_, mul2(v0_, v0_)); \
        ull t1_ = fma2(mu12_, NTWO, fma2(v3_, TWO, C2p)); \
        ull t2_ = fma2(msum_, NONE, add2(v2_, C2p)); \
        ull num_ = mul2(fma2(mu12_, TWO, C1p), t1_); \
        ull den_ = mul2(add2(msum_, C1p), t2_); \
        if (lo_ok) acc0 += __fdividef(lo2(num_), lo2(den_)); \
        if (hi_ok) acc1 += __fdividef(hi2(num_), hi2(den_)); \
    } \
} while(0)

// Pair-step: P literal in {0,2,4}. Commits rows P+4,P+5 (one group), one wait +
// one syncwarp, then computes rows P and P+1 with no barrier between them.
#define PAIR_STEP(P, DOOUT0, DOOUT1, DOLOAD) do { \
    if (DOLOAD && lane18){ \
        cpa16(sxw + (((P)+4)%NSLOT)*(SEGF*4) + lane16, xsrc + (P)*2048); \
        cpa16(syw + (((P)+4)%NSLOT)*(SEGF*4) + lane16, ysrc + (P)*2048); \
        cpa16(sxw + (((P)+5)%NSLOT)*(SEGF*4) + lane16, xsrc + ((P)+1)*2048); \
        cpa16(syw + (((P)+5)%NSLOT)*(SEGF*4) + lane16, ysrc + ((P)+1)*2048); \
    } \
    cpa_commit(); \
    cpa_wait2(); \
    __syncwarp(); \
    ROW_COMPUTE(P, DOOUT0); \
    ROW_COMPUTE((P)+1, DOOUT1); \
} while(0)

__global__ void __launch_bounds__(256, 2)
k_ssim(const float* __restrict__ X, const float* __restrict__ Y,
       float* __restrict__ out, int nblk, double inv_n){
    // warp-private row rings: [warp][slot][72 floats] per tensor
    __shared__ float s_x[8][NSLOT][SEGF];
    __shared__ float s_y[8][NSLOT][SEGF];
    __shared__ float    smn[8], smx[8], sC[2];
    __shared__ double   sd[8];
    __shared__ unsigned s_tick;

    const int tid   = threadIdx.x;
    const int wid   = tid >> 5;
    const int lane  = tid & 31;
    const int wc0   = wid * 64;            // warp's first output column
    const int c0    = wc0 + lane * 2;      // this thread's first output column
    const int lane2 = lane * 2;            // float offset within segment
    const int bx    = blockIdx.x;
    const int strip = bx % NSTR;
    const int img   = bx / NSTR;
    const int base  = strip * STRIP;
    const float* xi = X + (size_t)img * (IMG_W * IMG_W);
    const float* yi = Y + (size_t)img * (IMG_W * IMG_W);
    const bool lo_ok = (c0     < OUT_W);
    const bool hi_ok = (c0 + 1 < OUT_W);
    const bool lane18 = (lane < 18);

    // cp.async source column for this lane (16B granule), clamped to row end
    const int scol   = min(wc0 + lane * 4, 508);
    const int lane16 = lane * 16;          // byte offset within segment

    // running source byte pointers -> row (group_start + 4)
    const char* xsrc = (const char*)(xi + (size_t)(base + 4) * IMG_W + scol);
    const char* ysrc = (const char*)(yi + (size_t)(base + 4) * IMG_W + scol);

    // smem u32 addresses of this warp's ring bases
    const unsigned sxw = (unsigned)__cvta_generic_to_shared(&s_x[wid][0][0]);
    const unsigned syw = (unsigned)__cvta_generic_to_shared(&s_y[wid][0][0]);
    const float (*swx)[SEGF] = s_x[wid];
    const float (*swy)[SEGF] = s_y[wid];

    // ================= phase 1: strip min/max scan (MLP-4, also warms L2) ====
    {
        float mn0 = 3.4028235e38f, mx0 = -3.4028235e38f;
        float mn1 = mn0, mx1 = mx0, mn2 = mn0, mx2 = mx0, mn3 = mn0, mx3 = mx0;
        const float4* xs = (const float4*)(xi + (size_t)base * IMG_W);
        const int n4s = NROWS * (IMG_W / 4);   // 174 rows * 128 float4 = 22272
        int i = tid;
        for (; i + 768 < n4s; i += 1024){
            float4 a = xs[i];
            float4 b = xs[i + 256];
            float4 c = xs[i + 512];
            float4 d = xs[i + 768];
            mn0 = fminf(mn0, fminf(fminf(a.x, a.y), fminf(a.z, a.w)));
            mx0 = fmaxf(mx0, fmaxf(fmaxf(a.x, a.y), fmaxf(a.z, a.w)));
            mn1 = fminf(mn1, fminf(fminf(b.x, b.y), fminf(b.z, b.w)));
            mx1 = fmaxf(mx1, fmaxf(fmaxf(b.x, b.y), fmaxf(b.z, b.w)));
            mn2 = fminf(mn2, fminf(fminf(c.x, c.y), fminf(c.z, c.w)));
            mx2 = fmaxf(mx2, fmaxf(fmaxf(c.x, c.y), fmaxf(c.z, c.w)));
            mn3 = fminf(mn3, fminf(fminf(d.x, d.y), fminf(d.z, d.w)));
            mx3 = fmaxf(mx3, fmaxf(fmaxf(d.x, d.y), fmaxf(d.z, d.w)));
        }
        for (; i < n4s; i += 256){
            float4 a = xs[i];
            mn0 = fminf(mn0, fminf(fminf(a.x, a.y), fminf(a.z, a.w)));
            mx0 = fmaxf(mx0, fmaxf(fmaxf(a.x, a.y), fmaxf(a.z, a.w)));
        }
        float mn = fminf(fminf(mn0, mn1), fminf(mn2, mn3));
        float mx = fmaxf(fmaxf(mx0, mx1), fmaxf(mx2, mx3));
        #pragma unroll
        for (int o = 16; o > 0; o >>= 1){
            mn = fminf(mn, __shfl_xor_sync(0xFFFFFFFFu, mn, o));
            mx = fmaxf(mx, __shfl_xor_sync(0xFFFFFFFFu, mx, o));
        }
        if (lane == 0){ smn[wid] = mn; smx[wid] = mx; }
    }

    // prologue cp.asyncs issued BEFORE the barrier spin: their DRAM fetch
    // overlaps the wait. rows base+0,base+1 -> group A; base+2,base+3 -> group B.
    if (lane18){
        cpa16(sxw + 0*(SEGF*4) + lane16, xsrc - 4*2048);
        cpa16(syw + 0*(SEGF*4) + lane16, ysrc - 4*2048);
        cpa16(sxw + 1*(SEGF*4) + lane16, xsrc - 3*2048);
        cpa16(syw + 1*(SEGF*4) + lane16, ysrc - 3*2048);
    }
    cpa_commit();
    if (lane18){
        cpa16(sxw + 2*(SEGF*4) + lane16, xsrc - 2*2048);
        cpa16(syw + 2*(SEGF*4) + lane16, ysrc - 2*2048);
        cpa16(sxw + 3*(SEGF*4) + lane16, xsrc - 1*2048);
        cpa16(syw + 3*(SEGF*4) + lane16, ysrc - 1*2048);
    }
    cpa_commit();

    // publish partial + soft grid barrier (all 288 blocks co-resident at occ-2)
    __syncthreads();
    if (tid == 0){
        float mn = smn[0], mx = smx[0];
        #pragma unroll
        for (int w = 1; w < 8; ++w){ mn = fminf(mn, smn[w]); mx = fmaxf(mx, smx[w]); }
        g_mnp[bx] = mn;
        g_mxp[bx] = mx;
        __threadfence();
        atomicAdd(&g_bar, 1u);
        while (atomicAdd(&g_bar, 0u) < (unsigned)nblk) __nanosleep(64);
    }
    __syncthreads();
    __threadfence();

    // ---- reduce the global minmax partials -> C1, C2 ----
    {
        float mn = 3.4028235e38f, mx = -3.4028235e38f;
        for (int i = tid; i < nblk; i += 256){
            mn = fminf(mn, g_mnp[i]);
            mx = fmaxf(mx, g_mxp[i]);
        }
        #pragma unroll
        for (int o = 16; o > 0; o >>= 1){
            mn = fminf(mn, __shfl_xor_sync(0xFFFFFFFFu, mn, o));
            mx = fmaxf(mx, __shfl_xor_sync(0xFFFFFFFFu, mx, o));
        }
        if (lane == 0){ smn[wid] = mn; smx[wid] = mx; }
        __syncthreads();
        if (tid == 0){
            mn = smn[0]; mx = smx[0];
            #pragma unroll
            for (int w = 1; w < 8; ++w){ mn = fminf(mn, smn[w]); mx = fmaxf(mx, smx[w]); }
            float Ldyn = (mx > 128.0f ? 255.0f : 1.0f) - (mn < -0.5f ? -1.0f : 0.0f);
            sC[0] = (0.01f * Ldyn) * (0.01f * Ldyn);
            sC[1] = (0.03f * Ldyn) * (0.03f * Ldyn);
        }
        __syncthreads();
    }

    const float C1 = sC[0], C2 = sC[1];
    const ull W0  = pk2(GW0, GW0), W1 = pk2(GW1, GW1);
    const ull W2  = pk2(GW2, GW2), W3 = pk2(GW3, GW3);
    const ull C1p = pk2(C1, C1),   C2p = pk2(C2, C2);
    const ull TWO = pk2(2.0f, 2.0f), NTWO = pk2(-2.0f, -2.0f), NONE = pk2(-1.0f, -1.0f);

    ull ring[6][4];
    float acc0 = 0.0f, acc1 = 0.0f;

    // ---- group 0 (rows 0..5): warm-up, first output at row 5; loads rows 4..9 ----
    PAIR_STEP(0, 0, 0, 1);
    PAIR_STEP(2, 0, 0, 1);
    PAIR_STEP(4, 0, 1, 1);
    xsrc += 6*2048; ysrc += 6*2048;

    // ---- middle groups (rows 6..167): fully clean; loads rows 10..171 ----
    #pragma unroll 1
    for (int g = 0; g < 27; ++g){
        PAIR_STEP(0, 1, 1, 1);
        PAIR_STEP(2, 1, 1, 1);
        PAIR_STEP(4, 1, 1, 1);
        xsrc += 6*2048; ysrc += 6*2048;
    }

    // ---- tail group (rows 168..173): loads rows 172,173 then stop ----
    PAIR_STEP(0, 1, 1, 1);   // loads rows 172,173
    PAIR_STEP(2, 1, 1, 0);
    PAIR_STEP(4, 1, 1, 0);

    // ---- block reduction -> partial; last block finishes ----
    float acc = acc0 + acc1;
    #pragma unroll
    for (int o = 16; o > 0; o >>= 1)
        acc += __shfl_xor_sync(0xFFFFFFFFu, acc, o);
    if (lane == 0) smn[wid] = acc;
    __syncthreads();
    if (tid == 0){
        float s = smn[0];
        #pragma unroll
        for (int w = 1; w < 8; ++w) s += smn[w];
        g_part[bx] = s;
        __threadfence();
        s_tick = atomicAdd(&g_done, 1u);
    }
    __syncthreads();

    if (s_tick == (unsigned)(nblk - 1)){
        double s = 0.0;
        for (int i = tid; i < nblk; i += 256) s += (double)g_part[i];
        #pragma unroll
        for (int o = 16; o > 0; o >>= 1)
            s += __shfl_xor_sync(0xFFFFFFFFu, s, o);
        if (lane == 0) sd[wid] = s;
        __syncthreads();
        if (tid == 0){
            double t = 0.0;
            #pragma unroll
            for (int w = 0; w < 8; ++w) t += sd[w];
            out[0] = (float)((1.0 - t * inv_n) * 0.5);
            g_done = 0u;   // reset for next graph replay
            g_bar  = 0u;
        }
    }
}

// ---------------- launch --------------------------------------------------------
extern "C" void kernel_launch(void* const* d_in, const int* in_sizes, int n_in,
                              void* d_out, int out_size){
    const float* X = (const float*)d_in[0];  // y_pred
    const float* Y = (const float*)d_in[1];  // y_true

    const int nelem = in_sizes[0];
    const int nimg  = nelem / (IMG_W * IMG_W);
    const int nblk  = NSTR * nimg;           // 288 <= co-resident capacity 296
    const double n_out = (double)nimg * (double)OUT_W * (double)OUT_W;

    k_ssim<<<nblk, 256>>>(X, Y, (float*)d_out, nblk, 1.0 / n_out);
}

// round 17
// speedup vs baseline: 1.0231x; 1.0231x over previous
#include <cuda_runtime.h>
#include <cstdint>

typedef unsigned long long ull;

#define IMG_W 512
#define OUT_W 507
#define NSTR  3       // strips per image
#define STRIP 169     // output rows per strip (3*169 = 507 exact)
#define NROWS 174     // input rows per strip (STRIP + 5), divisible by 6
#define NB_MM 1184
#define SEGF  72      // floats per warp row segment (64 + 6 halo + 2 pad)
#define NSLOT 6       // smem ring slots per warp

// ---------------- device-global scratch (no allocs) --------------------------
__device__ float    g_mn[NB_MM], g_mx[NB_MM];
__device__ float    g_part[512];
__device__ unsigned g_done;          // zero-init; last block resets each run

// ---------------- packed f32x2 helpers (sm_103a) ------------------------------
static __device__ __forceinline__ ull pk2(float a, float b){
    ull r; asm("mov.b64 %0, {%1, %2};" : "=l"(r) : "f"(a), "f"(b)); return r;
}
static __device__ __forceinline__ ull mul2(ull a, ull b){
    ull r; asm("mul.rn.f32x2 %0, %1, %2;" : "=l"(r) : "l"(a), "l"(b)); return r;
}
static __device__ __forceinline__ ull add2(ull a, ull b){
    ull r; asm("add.rn.f32x2 %0, %1, %2;" : "=l"(r) : "l"(a), "l"(b)); return r;
}
static __device__ __forceinline__ ull fma2(ull a, ull b, ull c){
    ull r; asm("fma.rn.f32x2 %0, %1, %2, %3;" : "=l"(r) : "l"(a), "l"(b), "l"(c)); return r;
}
static __device__ __forceinline__ float lo2(ull a){ return __uint_as_float((unsigned)a); }
static __device__ __forceinline__ float hi2(ull a){ return __uint_as_float((unsigned)(a >> 32)); }

static __device__ __forceinline__ void cpa16(unsigned dst, const void* src){
    asm volatile("cp.async.ca.shared.global [%0], [%1], 16;" :: "r"(dst), "l"(src) : "memory");
}
static __device__ __forceinline__ void cpa_commit(){
    asm volatile("cp.async.commit_group;" ::: "memory");
}
static __device__ __forceinline__ void cpa_wait2(){
    asm volatile("cp.async.wait_group 2;" ::: "memory");
}

// ---------------- gaussian weights (w_size=6, sigma=1.5, normalized) ---------
#define GW0 0.03802585f
#define GW1 0.11551231f
#define GW2 0.22498725f
#define GW3 0.28097506f

// ---------------- min/max partials kernel -------------------------------------
__global__ void k_minmax(const float4* __restrict__ x, int n4){
    float mn = 3.4028235e38f, mx = -3.4028235e38f;
    int stride = gridDim.x * blockDim.x;
    for (int i = blockIdx.x * blockDim.x + threadIdx.x; i < n4; i += stride){
        float4 v = x[i];
        mn = fminf(mn, fminf(fminf(v.x, v.y), fminf(v.z, v.w)));
        mx = fmaxf(mx, fmaxf(fmaxf(v.x, v.y), fmaxf(v.z, v.w)));
    }
    #pragma unroll
    for (int o = 16; o > 0; o >>= 1){
        mn = fminf(mn, __shfl_xor_sync(0xFFFFFFFFu, mn, o));
        mx = fmaxf(mx, __shfl_xor_sync(0xFFFFFFFFu, mx, o));
    }
    __shared__ float smn[8], smx[8];
    int wid = threadIdx.x >> 5, lane = threadIdx.x & 31;
    if (lane == 0){ smn[wid] = mn; smx[wid] = mx; }
    __syncthreads();
    if (threadIdx.x == 0){
        mn = smn[0]; mx = smx[0];
        #pragma unroll
        for (int w = 1; w < 8; ++w){ mn = fminf(mn, smn[w]); mx = fmaxf(mx, smx[w]); }
        g_mn[blockIdx.x] = mn;
        g_mx[blockIdx.x] = mx;
    }
}

// Vertical 6-tap packed MAC (broadcast weights, aligned operands, no shifts)
#define VMAC(d, v0, v1, v2, v3, v4, v5) \
    d = mul2((v0), W0); d = fma2((v1), W1, d); d = fma2((v2), W2, d); \
    d = fma2((v3), W3, d); d = fma2((v4), W2, d); d = fma2((v5), W1, d)

// Even/odd horizontal 6-tap over packed lanes (cols c,c+1).
// Packed part (even taps): uses aligned pairs P0..P2 with broadcast weights.
// Scalar part (odd taps): 6 FFMA-with-immediate on free register halves.
//   out_lo = GW0*a0+GW2*a2+GW2*a4 (packed) + GW1*a1+GW3*a3+GW1*a5 (scalar)
//   out_hi = GW0*a1+GW2*a3+GW2*a5 (packed) + GW1*a2+GW3*a4+GW1*a6 (scalar)
#define HCONV(DST, P0, P1, P2, lA1, lA3, lA5, hA2, hA4, hA6) do { \
    ull d_ = mul2((P0), W0); \
    d_ = fma2((P1), W2, d_); \
    d_ = fma2((P2), W2, d_); \
    float dl_ = lo2(d_), dh_ = hi2(d_); \
    dl_ = fmaf((lA1), GW1, dl_); \
    dl_ = fmaf((lA3), GW3, dl_); \
    dl_ = fmaf((lA5), GW1, dl_); \
    dh_ = fmaf((hA2), GW1, dh_); \
    dh_ = fmaf((hA4), GW3, dh_); \
    dh_ = fmaf((hA6), GW1, dh_); \
    DST = pk2(dl_, dh_); \
} while(0)

// Compute one row from smem slot P%6; horizontal conv into ring[P]; optional output.
#define ROW_COMPUTE(P, DOOUT) do { \
    { \
        const float* bx_ = &swx[(P)%NSLOT][lane2]; \
        const float* by_ = &swy[(P)%NSLOT][lane2]; \
        float2 X0_ = *(const float2*)(bx_    ); \
        float2 X1_ = *(const float2*)(bx_ + 2); \
        float2 X2_ = *(const float2*)(bx_ + 4); \
        float2 X3_ = *(const float2*)(bx_ + 6); \
        float2 Y0_ = *(const float2*)(by_    ); \
        float2 Y1_ = *(const float2*)(by_ + 2); \
        float2 Y2_ = *(const float2*)(by_ + 4); \
        float2 Y3_ = *(const float2*)(by_ + 6); \
        ull xp0_ = pk2(X0_.x, X0_.y), xp1_ = pk2(X1_.x, X1_.y); \
        ull xp2_ = pk2(X2_.x, X2_.y), xp3_ = pk2(X3_.x, X3_.y); \
        ull yp0_ = pk2(Y0_.x, Y0_.y), yp1_ = pk2(Y1_.x, Y1_.y); \
        ull yp2_ = pk2(Y2_.x, Y2_.y), yp3_ = pk2(Y3_.x, Y3_.y); \
        ull pp0_ = fma2(yp0_, yp0_, mul2(xp0_, xp0_)); \
        ull pp1_ = fma2(yp1_, yp1_, mul2(xp1_, xp1_)); \
        ull pp2_ = fma2(yp2_, yp2_, mul2(xp2_, xp2_)); \
        ull pp3_ = fma2(yp3_, yp3_, mul2(xp3_, xp3_)); \
        ull qq0_ = mul2(xp0_, yp0_), qq1_ = mul2(xp1_, yp1_); \
        ull qq2_ = mul2(xp2_, yp2_), qq3_ = mul2(xp3_, yp3_); \
        HCONV(ring[(P)][0], xp0_, xp1_, xp2_, \
              X0_.y, X1_.y, X2_.y,  X1_.x, X2_.x, X3_.x); \
        HCONV(ring[(P)][1], yp0_, yp1_, yp2_, \
              Y0_.y, Y1_.y, Y2_.y,  Y1_.x, Y2_.x, Y3_.x); \
        HCONV(ring[(P)][2], pp0_, pp1_, pp2_, \
              hi2(pp0_), hi2(pp1_), hi2(pp2_),  lo2(pp1_), lo2(pp2_), lo2(pp3_)); \
        HCONV(ring[(P)][3], qq0_, qq1_, qq2_, \
              hi2(qq0_), hi2(qq1_), hi2(qq2_),  lo2(qq1_), lo2(qq2_), lo2(qq3_)); \
    } \
    if (DOOUT){ \
        ull v0_, v1_, v2_, v3_; \
        VMAC(v0_, ring[((P)+1)%6][0], ring[((P)+2)%6][0], ring[((P)+3)%6][0], ring[((P)+4)%6][0], ring[((P)+5)%6][0], ring[(P)][0]); \
        VMAC(v1_, ring[((P)+1)%6][1], ring[((P)+2)%6][1], ring[((P)+3)%6][1], ring[((P)+4)%6][1], ring[((P)+5)%6][1], ring[(P)][1]); \
        VMAC(v2_, ring[((P)+1)%6][2], ring[((P)+2)%6][2], ring[((P)+3)%6][2], ring[((P)+4)%6][2], ring[((P)+5)%6][2], ring[(P)][2]); \
        VMAC(v3_, ring[((P)+1)%6][3], ring[((P)+2)%6][3], ring[((P)+3)%6][3], ring[((P)+4)%6][3], ring[((P)+5)%6][3], ring[(P)][3]); \
        ull mu12_ = mul2(v0_, v1_); \
        ull msum_ = fma2(v1_, v1_, mul2(v0_, v0_)); \
        ull t1_ = fma2(mu12_, NTWO, fma2(v3_, TWO, C2p)); \
        ull t2_ = fma2(msum_, NONE, add2(v2_, C2p)); \
        ull num_ = mul2(fma2(mu12_, TWO, C1p), t1_); \
        ull den_ = mul2(add2(msum_, C1p), t2_); \
        if (lo_ok) acc0 += __fdividef(lo2(num_), lo2(den_)); \
        if (hi_ok) acc1 += __fdividef(hi2(num_), hi2(den_)); \
    } \
} while(0)

// Pair-step: P literal in {0,2,4}. Commits rows P+4,P+5 (one group), one wait +
// one syncwarp, then computes rows P and P+1 with no barrier between them.
#define PAIR_STEP(P, DOOUT0, DOOUT1, DOLOAD) do { \
    if (DOLOAD && lane18){ \
        cpa16(sxw + (((P)+4)%NSLOT)*(SEGF*4) + lane16, xsrc + (P)*2048); \
        cpa16(syw + (((P)+4)%NSLOT)*(SEGF*4) + lane16, ysrc + (P)*2048); \
        cpa16(sxw + (((P)+5)%NSLOT)*(SEGF*4) + lane16, xsrc + ((P)+1)*2048); \
        cpa16(syw + (((P)+5)%NSLOT)*(SEGF*4) + lane16, ysrc + ((P)+1)*2048); \
    } \
    cpa_commit(); \
    cpa_wait2(); \
    __syncwarp(); \
    ROW_COMPUTE(P, DOOUT0); \
    ROW_COMPUTE((P)+1, DOOUT1); \
} while(0)

__global__ void __launch_bounds__(256, 2)
k_ssim(const float* __restrict__ X, const float* __restrict__ Y,
       float* __restrict__ out, int nblk, double inv_n){
    // warp-private row rings: [warp][slot][72 floats] per tensor
    __shared__ float s_x[8][NSLOT][SEGF];
    __shared__ float s_y[8][NSLOT][SEGF];
    __shared__ float    smn[8], smx[8], sC[2];
    __shared__ double   sd[8];
    __shared__ unsigned s_tick;

    const int tid   = threadIdx.x;
    const int wid   = tid >> 5;
    const int lane  = tid & 31;
    const int wc0   = wid * 64;            // warp's first output column
    const int c0    = wc0 + lane * 2;      // this thread's first output column
    const int lane2 = lane * 2;            // float offset within segment
    const int bx    = blockIdx.x;
    const int strip = bx % NSTR;
    const int img   = bx / NSTR;
    const int base  = strip * STRIP;
    const float* xi = X + (size_t)img * (IMG_W * IMG_W);
    const float* yi = Y + (size_t)img * (IMG_W * IMG_W);
    const bool lo_ok = (c0     < OUT_W);
    const bool hi_ok = (c0 + 1 < OUT_W);
    const bool lane18 = (lane < 18);

    // cp.async source column for this lane (16B granule), clamped to row end
    const int scol   = min(wc0 + lane * 4, 508);
    const int lane16 = lane * 16;          // byte offset within segment

    // running source byte pointers -> row (group_start + 4)
    const char* xsrc = (const char*)(xi + (size_t)(base + 4) * IMG_W + scol);
    const char* ysrc = (const char*)(yi + (size_t)(base + 4) * IMG_W + scol);

    // smem u32 addresses of this warp's ring bases
    const unsigned sxw = (unsigned)__cvta_generic_to_shared(&s_x[wid][0][0]);
    const unsigned syw = (unsigned)__cvta_generic_to_shared(&s_y[wid][0][0]);
    const float (*swx)[SEGF] = s_x[wid];
    const float (*swy)[SEGF] = s_y[wid];

    // ---- reduce min/max partials -> C1, C2 ----
    {
        float mn = 3.4028235e38f, mx = -3.4028235e38f;
        for (int i = tid; i < NB_MM; i += 256){
            mn = fminf(mn, g_mn[i]);
            mx = fmaxf(mx, g_mx[i]);
        }
        #pragma unroll
        for (int o = 16; o > 0; o >>= 1){
            mn = fminf(mn, __shfl_xor_sync(0xFFFFFFFFu, mn, o));
            mx = fmaxf(mx, __shfl_xor_sync(0xFFFFFFFFu, mx, o));
        }
        if (lane == 0){ smn[wid] = mn; smx[wid] = mx; }
    }

    // prologue: rows base+0,base+1 -> group A (slots 0,1); rows base+2,base+3 -> group B (slots 2,3)
    if (lane18){
        cpa16(sxw + 0*(SEGF*4) + lane16, xsrc - 4*2048);
        cpa16(syw + 0*(SEGF*4) + lane16, ysrc - 4*2048);
        cpa16(sxw + 1*(SEGF*4) + lane16, xsrc - 3*2048);
        cpa16(syw + 1*(SEGF*4) + lane16, ysrc - 3*2048);
    }
    cpa_commit();
    if (lane18){
        cpa16(sxw + 2*(SEGF*4) + lane16, xsrc - 2*2048);
        cpa16(syw + 2*(SEGF*4) + lane16, ysrc - 2*2048);
        cpa16(sxw + 3*(SEGF*4) + lane16, xsrc - 1*2048);
        cpa16(syw + 3*(SEGF*4) + lane16, ysrc - 1*2048);
    }
    cpa_commit();

    __syncthreads();
    if (tid == 0){
        float mn = smn[0], mx = smx[0];
        #pragma unroll
        for (int w = 1; w < 8; ++w){ mn = fminf(mn, smn[w]); mx = fmaxf(mx, smx[w]); }
        float Ldyn = (mx > 128.0f ? 255.0f : 1.0f) - (mn < -0.5f ? -1.0f : 0.0f);
        sC[0] = (0.01f * Ldyn) * (0.01f * Ldyn);
        sC[1] = (0.03f * Ldyn) * (0.03f * Ldyn);
    }
    __syncthreads();

    const float C1 = sC[0], C2 = sC[1];
    const ull W0  = pk2(GW0, GW0), W1 = pk2(GW1, GW1);
    const ull W2  = pk2(GW2, GW2), W3 = pk2(GW3, GW3);
    const ull C1p = pk2(C1, C1),   C2p = pk2(C2, C2);
    const ull TWO = pk2(2.0f, 2.0f), NTWO = pk2(-2.0f, -2.0f), NONE = pk2(-1.0f, -1.0f);

    ull ring[6][4];
    float acc0 = 0.0f, acc1 = 0.0f;

    // ---- group 0 (rows 0..5): warm-up, first output at row 5; loads rows 4..9 ----
    PAIR_STEP(0, 0, 0, 1);
    PAIR_STEP(2, 0, 0, 1);
    PAIR_STEP(4, 0, 1, 1);
    xsrc += 6*2048; ysrc += 6*2048;

    // ---- middle groups (rows 6..167): fully clean; loads rows 10..171 ----
    #pragma unroll 1
    for (int g = 0; g < 27; ++g){
        PAIR_STEP(0, 1, 1, 1);
        PAIR_STEP(2, 1, 1, 1);
        PAIR_STEP(4, 1, 1, 1);
        xsrc += 6*2048; ysrc += 6*2048;
    }

    // ---- tail group (rows 168..173): loads rows 172,173 then stop ----
    PAIR_STEP(0, 1, 1, 1);   // loads rows 172,173
    PAIR_STEP(2, 1, 1, 0);
    PAIR_STEP(4, 1, 1, 0);

    // ---- block reduction -> partial; last block finishes ----
    float acc = acc0 + acc1;
    #pragma unroll
    for (int o = 16; o > 0; o >>= 1)
        acc += __shfl_xor_sync(0xFFFFFFFFu, acc, o);
    if (lane == 0) smn[wid] = acc;
    __syncthreads();
    if (tid == 0){
        float s = smn[0];
        #pragma unroll
        for (int w = 1; w < 8; ++w) s += smn[w];
        g_part[bx] = s;
        __threadfence();
        s_tick = atomicAdd(&g_done, 1u);
    }
    __syncthreads();

    if (s_tick == (unsigned)(nblk - 1)){
        double s = 0.0;
        for (int i = tid; i < nblk; i += 256) s += (double)g_part[i];
        #pragma unroll
        for (int o = 16; o > 0; o >>= 1)
            s += __shfl_xor_sync(0xFFFFFFFFu, s, o);
        if (lane == 0) sd[wid] = s;
        __syncthreads();
        if (tid == 0){
            double t = 0.0;
            #pragma unroll
            for (int w = 0; w < 8; ++w) t += sd[w];
            out[0] = (float)((1.0 - t * inv_n) * 0.5);
            g_done = 0u;   // reset for next graph replay
        }
    }
}

// ---------------- launch --------------------------------------------------------
extern "C" void kernel_launch(void* const* d_in, const int* in_sizes, int n_in,
                              void* d_out, int out_size){
    const float* X = (const float*)d_in[0];  // y_pred
    const float* Y = (const float*)d_in[1];  // y_true

    const int nelem = in_sizes[0];
    const int nimg  = nelem / (IMG_W * IMG_W);
    const int nblk  = NSTR * nimg;
    const double n_out = (double)nimg * (double)OUT_W * (double)OUT_W;

    k_minmax<<<NB_MM, 256>>>((const float4*)X, nelem / 4);
    k_ssim<<<nblk, 256>>>(X, Y, (float*)d_out, nblk, 1.0 / n_out);
}